// round 14
// baseline (speedup 1.0000x reference)
#include <cuda_runtime.h>
#include <cuda_fp16.h>
#include <cstdint>

#define BB 8
#define TT 256
#define LL 48
#define FDIM 1024
#define WDIM 512
#define HD 512
#define OD 512
#define OUT_OFF (BB*TT*OD)                 /* 1048576 floats */
#define H2V_ELEMS (BB*TT*LL*HD)            /* 50331648 floats */

// ---------------- scratch (no allocations allowed) ----------------
__device__ float g_henc[BB*LL*HD];         // relu(word @ Ww + bw)
__device__ float g_v[BB*TT*HD];            // relu(frame @ Wf + bf)
__device__ float g_fww[BB*TT*HD];          // sum_l h2v * word

// ---------------- helpers ----------------
__device__ __forceinline__ float tanh_fast(float x) {
    float y; asm("tanh.approx.f32 %0, %1;" : "=f"(y) : "f"(x)); return y;
}
__device__ __forceinline__ uint32_t pack_h2(float lo, float hi) {
    __half2 h = __floats2half2_rn(lo, hi);
    return *(uint32_t*)&h;
}
__device__ __forceinline__ void mma_f16(float* c, const uint32_t* a,
                                        uint32_t b0, uint32_t b1) {
    asm volatile("mma.sync.aligned.m16n8k16.row.col.f32.f16.f16.f32 "
                 "{%0,%1,%2,%3}, {%4,%5,%6,%7}, {%8,%9}, {%0,%1,%2,%3};"
                 : "+f"(c[0]), "+f"(c[1]), "+f"(c[2]), "+f"(c[3])
                 : "r"(a[0]), "r"(a[1]), "r"(a[2]), "r"(a[3]),
                   "r"(b0), "r"(b1));
}

// ======== fp16 tensor-core GEMM: 64x128 tile, triple-buffer, masked =======
// 256 threads, 8 warps (2m x 4n), warp tile 32x32. K chunks of 32 (16 k2).
// MASK: 0 = none; 1 = skip tile if t-local >= flen[batch] (frame encoder);
//       2 = write zeros + return if masked (out GEMM). batch = m0>>8.
#define GF_AS 1280     /* 64*20 u32 per buffer */
#define GF_BS 2176     /* 16*136 u32 per buffer */
#define GF_SMEM ((3*GF_AS + 3*GF_BS)*4)    /* 41472 bytes */

template<bool RELU, bool BIAS, int MASK>
__global__ __launch_bounds__(256) void gemm_f16k(
    const float* __restrict__ A, const float* __restrict__ W,
    const float* __restrict__ bias, float* __restrict__ C,
    const int* __restrict__ flen, int M, int N, int K)
{
    extern __shared__ uint32_t smu[];
    uint32_t* As = smu;                 // 3 buffers [64][20]
    uint32_t* Bs = smu + 3*GF_AS;       // 3 buffers [16][136]
    const int tid = threadIdx.x;
    const int m0 = blockIdx.y * 64, n0 = blockIdx.x * 128;

    if (MASK) {
        int bt = m0 >> 8, tloc = m0 & 255;
        if (tloc >= flen[bt]) {
            if (MASK == 2) {
                float4 z = make_float4(0.f, 0.f, 0.f, 0.f);
                for (int i = tid; i < 64 * 32; i += 256) {
                    int r = i >> 5, c4 = (i & 31) << 2;
                    *(float4*)(C + (size_t)(m0 + r) * N + n0 + c4) = z;
                }
            }
            return;
        }
    }

    const int lane = tid & 31, wid = tid >> 5;
    const int g = lane >> 2, tig = lane & 3;
    const int wm = wid & 1, wn = wid >> 1;
    const int warp_m0 = wm * 32, warp_n0 = wn * 32;

    const int ar0 = tid >> 3,         ak0 = (tid & 7) << 2;
    const int ar1 = (tid + 256) >> 3, ak1 = ((tid + 256) & 7) << 2;
    const int bk0 = tid >> 5;
    const int bnq = (tid & 31) << 2;

    float c[2][4][4];
    #pragma unroll
    for (int mi = 0; mi < 2; ++mi)
        #pragma unroll
        for (int nf = 0; nf < 4; ++nf)
            #pragma unroll
            for (int j = 0; j < 4; ++j) c[mi][nf][j] = 0.f;

    struct Stage { float4 ra0, ra1, b0a, b0b, b1a, b1b; };
    Stage s0, s1;

    auto ldg_chunk = [&](int k0, Stage& st) {
        st.ra0 = *(const float4*)(A + (size_t)(m0 + ar0) * K + k0 + ak0);
        st.ra1 = *(const float4*)(A + (size_t)(m0 + ar1) * K + k0 + ak1);
        st.b0a = *(const float4*)(W + (size_t)(k0 + 2*bk0)      * N + n0 + bnq);
        st.b0b = *(const float4*)(W + (size_t)(k0 + 2*bk0 + 1)  * N + n0 + bnq);
        st.b1a = *(const float4*)(W + (size_t)(k0 + 2*(bk0+8))     * N + n0 + bnq);
        st.b1b = *(const float4*)(W + (size_t)(k0 + 2*(bk0+8) + 1) * N + n0 + bnq);
    };
    auto sts_chunk = [&](const Stage& st, int bsel) {
        uint32_t* as = As + bsel * GF_AS;
        uint32_t* bs = Bs + bsel * GF_BS;
        *(uint2*)&as[ar0 * 20 + (ak0 >> 1)] =
            make_uint2(pack_h2(st.ra0.x, st.ra0.y), pack_h2(st.ra0.z, st.ra0.w));
        *(uint2*)&as[ar1 * 20 + (ak1 >> 1)] =
            make_uint2(pack_h2(st.ra1.x, st.ra1.y), pack_h2(st.ra1.z, st.ra1.w));
        uint4 p0, p1;
        p0.x = pack_h2(st.b0a.x, st.b0b.x); p0.y = pack_h2(st.b0a.y, st.b0b.y);
        p0.z = pack_h2(st.b0a.z, st.b0b.z); p0.w = pack_h2(st.b0a.w, st.b0b.w);
        p1.x = pack_h2(st.b1a.x, st.b1b.x); p1.y = pack_h2(st.b1a.y, st.b1b.y);
        p1.z = pack_h2(st.b1a.z, st.b1b.z); p1.w = pack_h2(st.b1a.w, st.b1b.w);
        *(uint4*)&bs[bk0 * 136 + bnq]       = p0;
        *(uint4*)&bs[(bk0 + 8) * 136 + bnq] = p1;
    };
    auto mma_chunk = [&](int bsel) {
        const uint32_t* as = As + bsel * GF_AS;
        const uint32_t* bs = Bs + bsel * GF_BS;
        #pragma unroll
        for (int ks = 0; ks < 2; ++ks) {
            const int base = ks * 8;
            uint32_t a[2][4];
            #pragma unroll
            for (int mi = 0; mi < 2; ++mi) {
                int r0 = warp_m0 + mi * 16;
                a[mi][0] = as[(r0 + g)     * 20 + base + tig];
                a[mi][1] = as[(r0 + 8 + g) * 20 + base + tig];
                a[mi][2] = as[(r0 + g)     * 20 + base + tig + 4];
                a[mi][3] = as[(r0 + 8 + g) * 20 + base + tig + 4];
            }
            #pragma unroll
            for (int nf = 0; nf < 4; ++nf) {
                int cc = warp_n0 + nf * 8 + g;
                uint32_t b0 = bs[(base + tig)     * 136 + cc];
                uint32_t b1 = bs[(base + tig + 4) * 136 + cc];
                mma_f16(c[0][nf], a[0], b0, b1);
                mma_f16(c[1][nf], a[1], b0, b1);
            }
        }
    };

    const int nch = K >> 5;
    ldg_chunk(0, s0);
    sts_chunk(s0, 0);
    if (nch > 1) ldg_chunk(32, s1);
    __syncthreads();

    int bcur = 0, bnxt = 1, bnxt2 = 2;
    for (int gch = 0; gch < nch; gch += 2) {
        if (gch + 2 < nch) ldg_chunk((gch + 2) << 5, s0);
        mma_chunk(bcur);
        if (gch + 1 < nch) sts_chunk(s1, bnxt);
        __syncthreads();
        if (gch + 3 < nch) ldg_chunk((gch + 3) << 5, s1);
        if (gch + 1 < nch) mma_chunk(bnxt);
        if (gch + 2 < nch) sts_chunk(s0, bnxt2);
        __syncthreads();
        int t = bcur; bcur = bnxt2; bnxt2 = bnxt; bnxt = t;
    }

    #pragma unroll
    for (int mi = 0; mi < 2; ++mi) {
        #pragma unroll
        for (int nf = 0; nf < 4; ++nf) {
            int r0 = m0 + warp_m0 + mi * 16 + g;
            int cc = n0 + warp_n0 + nf * 8 + tig * 2;
            float o0 = c[mi][nf][0], o1 = c[mi][nf][1];
            float o2 = c[mi][nf][2], o3 = c[mi][nf][3];
            if (BIAS) {
                float bb0 = bias[cc], bb1 = bias[cc + 1];
                o0 += bb0; o1 += bb1; o2 += bb0; o3 += bb1;
            }
            if (RELU) {
                o0 = fmaxf(o0, 0.f); o1 = fmaxf(o1, 0.f);
                o2 = fmaxf(o2, 0.f); o3 = fmaxf(o3, 0.f);
            }
            *(float2*)(C + (size_t)r0 * N + cc)       = make_float2(o0, o1);
            *(float2*)(C + (size_t)(r0 + 8) * N + cc) = make_float2(o2, o3);
        }
    }
}

// ================= fused attention v9: v8 + 2 CTAs/SM ======================
// Identical to attn_v8 except __launch_bounds__(512, 2): two CTAs co-resident
// per SM (2 x 108 KB smem <= 227 KB) so build/epilogue/stall phases interleave.
#define AT_AM_U32  0                     /* 64*260 = 16640 u32 */
#define AT_B_U32   16640                 /* 2*8*520 = 8320 u32 */
#define AT_VT_F32  24960                 /* TPBmax*512 = 2048 f32 */
#define AT_SMEM    ((24960 + 2048) * 4)  /* 108032 bytes */
#define R_STRIDE   264

__global__ __launch_bounds__(512, 2) void attn_v9(
    const float* __restrict__ Wa, const float* __restrict__ word,
    const int* __restrict__ flen, const int* __restrict__ wlen,
    float* __restrict__ h2v_all, int write_h2v)
{
    extern __shared__ float sm[];
    const int tid = threadIdx.x;
    const int b  = blockIdx.y >> 8;
    const int yl = blockIdx.y & 255;
    const int fl = flen[b];

    int Lv = wlen[b]; if (Lv > LL) Lv = LL;
    const int lpsh = (Lv <= 16) ? 4 : (Lv <= 32) ? 5 : 6;
    const int lpmask = (1 << lpsh) - 1;
    const int TPB = 64 >> lpsh;                // 4 / 2 / 1
    const int t0 = yl * TPB;
    if (t0 >= TT) return;

    float* h2v = write_h2v ? h2v_all : nullptr;

    if (t0 >= fl) {       // fully masked t's: exact zeros
        float4 z = make_float4(0.f, 0.f, 0.f, 0.f);
        if (h2v) {
            for (int i = tid; i < TPB * LL * 128; i += 512) {
                int t = i / (LL * 128);
                int rem = i - t * (LL * 128);
                int l = rem >> 7, c4 = (rem & 127) << 2;
                *(float4*)&h2v[((size_t)(b * TT + t0 + t) * LL + l) * HD + c4] = z;
            }
        }
        for (int i = tid; i < TPB * 128; i += 512) {
            int t = i >> 7, c4 = (i & 127) << 2;
            *(float4*)&g_fww[(size_t)(b * TT + t0 + t) * HD + c4] = z;
        }
        return;
    }

    uint32_t* Am = (uint32_t*)sm + AT_AM_U32;     // [64][260]
    uint32_t* Bb = (uint32_t*)sm + AT_B_U32;      // 2 x [8][520]
    float*    vt = sm + AT_VT_F32;
    float*    R  = sm;                            // overlay, [64][264]

    // stage v rows
    for (int i = tid; i < TPB * 128; i += 512) {
        int tl = i >> 7, c4 = (i & 127) << 2;
        *(float4*)&vt[tl * 512 + c4] =
            *(const float4*)&g_v[(size_t)(b * TT + t0 + tl) * HD + c4];
    }
    __syncthreads();

    // build A once: tanh(v + henc) -> half2 k-pairs; zero padded l rows
    for (int i = tid; i < 64 * 128; i += 512) {
        int r = i >> 7, c4 = (i & 127) << 2;
        int tl = r >> lpsh, l = r & lpmask;
        uint2 pk = make_uint2(0u, 0u);
        if (l < Lv) {
            float4 hv = *(const float4*)&g_henc[(size_t)(b * LL + l) * HD + c4];
            const float* vp = &vt[tl * 512 + c4];
            float v0 = tanh_fast(vp[0] + hv.x);
            float v1 = tanh_fast(vp[1] + hv.y);
            float v2 = tanh_fast(vp[2] + hv.z);
            float v3 = tanh_fast(vp[3] + hv.w);
            pk.x = pack_h2(v0, v1);
            pk.y = pack_h2(v2, v3);
        }
        *(uint2*)&Am[r * 260 + (c4 >> 1)] = pk;
    }
    __syncthreads();

    const int lane = tid & 31, wid = tid >> 5;           // 16 warps
    const int g = lane >> 2, tig = lane & 3;
    const int wm = wid & 1, wn = wid >> 1;               // 2m x 8n
    const int warp_m0 = wm * 32, warp_n0 = wn * 64;
    const bool skip_hi = (lpsh == 6) && (wm == 1);

    float c[2][8][4];
    #pragma unroll
    for (int mi = 0; mi < 2; ++mi)
        #pragma unroll
        for (int nf = 0; nf < 8; ++nf)
            #pragma unroll
            for (int j = 0; j < 4; ++j) c[mi][nf][j] = 0.f;

    const int bk2l0 = tid >> 7;                // 0..3
    const int bk2l1 = (tid + 512) >> 7;        // 4..7
    const int bnq   = (tid & 127) << 2;        // 0..508
    float4 rbA0, rbB0, rbA1, rbB1;

    auto ldgB = [&](int gch) {
        const int k0 = gch << 4;
        rbA0 = *(const float4*)&Wa[(size_t)(k0 + 2*bk2l0)     * HD + bnq];
        rbB0 = *(const float4*)&Wa[(size_t)(k0 + 2*bk2l0 + 1) * HD + bnq];
        rbA1 = *(const float4*)&Wa[(size_t)(k0 + 2*bk2l1)     * HD + bnq];
        rbB1 = *(const float4*)&Wa[(size_t)(k0 + 2*bk2l1 + 1) * HD + bnq];
    };
    auto stsB = [&](int bsel) {
        uint32_t* bs = Bb + bsel * (8 * 520);
        uint4 p0, p1;
        p0.x = pack_h2(rbA0.x, rbB0.x); p0.y = pack_h2(rbA0.y, rbB0.y);
        p0.z = pack_h2(rbA0.z, rbB0.z); p0.w = pack_h2(rbA0.w, rbB0.w);
        p1.x = pack_h2(rbA1.x, rbB1.x); p1.y = pack_h2(rbA1.y, rbB1.y);
        p1.z = pack_h2(rbA1.z, rbB1.z); p1.w = pack_h2(rbA1.w, rbB1.w);
        *(uint4*)&bs[bk2l0 * 520 + bnq] = p0;
        *(uint4*)&bs[bk2l1 * 520 + bnq] = p1;
    };

    ldgB(0);
    stsB(0);
    __syncthreads();
    for (int gch = 0; gch < 32; ++gch) {
        if (gch < 31) ldgB(gch + 1);
        {
            const uint32_t* bs = Bb + (gch & 1) * (8 * 520);
            const int kof2 = gch << 3;
            uint32_t a[2][4];
            #pragma unroll
            for (int mi = 0; mi < 2; ++mi) {
                int r0 = warp_m0 + mi * 16;
                a[mi][0] = Am[(r0 + g)     * 260 + kof2 + tig];
                a[mi][1] = Am[(r0 + 8 + g) * 260 + kof2 + tig];
                a[mi][2] = Am[(r0 + g)     * 260 + kof2 + tig + 4];
                a[mi][3] = Am[(r0 + 8 + g) * 260 + kof2 + tig + 4];
            }
            #pragma unroll
            for (int nf = 0; nf < 8; ++nf) {
                int cc = warp_n0 + nf * 8 + g;
                uint32_t b0 = bs[tig * 520 + cc];
                uint32_t b1 = bs[(tig + 4) * 520 + cc];
                mma_f16(c[0][nf], a[0], b0, b1);
                if (!skip_hi) mma_f16(c[1][nf], a[1], b0, b1);
            }
        }
        if (gch < 31) stsB((gch + 1) & 1);
        __syncthreads();
    }

    // epilogue in two 256-col halves (R overlays dead A/B smem)
    const int myhalf = wn >> 2;
    for (int h = 0; h < 2; ++h) {
        if (myhalf == h) {
            #pragma unroll
            for (int mi = 0; mi < 2; ++mi) {
                if (mi == 1 && skip_hi) break;
                #pragma unroll
                for (int nf = 0; nf < 8; ++nf) {
                    int rr0 = warp_m0 + mi * 16 + g;
                    int cl  = (warp_n0 & 255) + nf * 8 + tig * 2;
                    *(float2*)&R[rr0 * R_STRIDE + cl] =
                        make_float2(fmaxf(c[mi][nf][0], 0.f), fmaxf(c[mi][nf][1], 0.f));
                    *(float2*)&R[(rr0 + 8) * R_STRIDE + cl] =
                        make_float2(fmaxf(c[mi][nf][2], 0.f), fmaxf(c[mi][nf][3], 0.f));
                }
            }
        }
        __syncthreads();

        const int col = tid & 255;
        const int tgpar = tid >> 8;
        for (int tg = tgpar; tg < TPB; tg += 2) {
            const int t = t0 + tg;
            const int rb2 = tg << lpsh;
            const int hg = h * 256 + col;
            float* hp = h2v ? (h2v + ((size_t)(b * TT + t) * LL) * HD + hg) : nullptr;
            if (t < fl) {
                float mx = 0.f;
                for (int l = 0; l < Lv; ++l)
                    mx = fmaxf(mx, R[(rb2 + l) * R_STRIDE + col]);
                float sum = 0.f;
                for (int l = 0; l < Lv; ++l) {
                    float e = __expf(R[(rb2 + l) * R_STRIDE + col] - mx);
                    sum += e;
                    R[(rb2 + l) * R_STRIDE + col] = e;
                }
                float inv = 1.0f / sum;
                const float* wp = word + ((size_t)b * LL) * WDIM + hg;
                float fww = 0.f;
                for (int l = 0; l < Lv; ++l) {
                    float w = R[(rb2 + l) * R_STRIDE + col] * inv;
                    if (hp) hp[(size_t)l * HD] = w;
                    fww += w * wp[(size_t)l * WDIM];
                }
                if (hp)
                    for (int l = Lv; l < LL; ++l) hp[(size_t)l * HD] = 0.f;
                g_fww[(size_t)(b * TT + t) * HD + hg] = fww;
            } else {
                if (hp)
                    for (int l = 0; l < LL; ++l) hp[(size_t)l * HD] = 0.f;
                g_fww[(size_t)(b * TT + t) * HD + hg] = 0.f;
            }
        }
        __syncthreads();
    }
}

// ---------------- launcher ----------------
extern "C" void kernel_launch(void* const* d_in, const int* in_sizes, int n_in,
                              void* d_out, int out_size) {
    const float* frame = (const float*)d_in[0];
    const float* word  = (const float*)d_in[1];
    const int*   flen  = (const int*)  d_in[2];
    const int*   wlen  = (const int*)  d_in[3];
    const float* Wf    = (const float*)d_in[4];
    const float* bf    = (const float*)d_in[5];
    const float* Ww    = (const float*)d_in[6];
    const float* bw    = (const float*)d_in[7];
    const float* Wa    = (const float*)d_in[8];
    const float* Wout  = (const float*)d_in[9];
    float* out = (float*)d_out;

    float *henc, *v, *fww;
    cudaGetSymbolAddress((void**)&henc, g_henc);
    cudaGetSymbolAddress((void**)&v,    g_v);
    cudaGetSymbolAddress((void**)&fww,  g_fww);

    cudaFuncSetAttribute(gemm_f16k<true, true, 0>,
                         cudaFuncAttributeMaxDynamicSharedMemorySize, GF_SMEM);
    cudaFuncSetAttribute(gemm_f16k<true, true, 1>,
                         cudaFuncAttributeMaxDynamicSharedMemorySize, GF_SMEM);
    cudaFuncSetAttribute(gemm_f16k<false, false, 2>,
                         cudaFuncAttributeMaxDynamicSharedMemorySize, GF_SMEM);
    cudaFuncSetAttribute(attn_v9,
                         cudaFuncAttributeMaxDynamicSharedMemorySize, AT_SMEM);

    // 1) word encoder: henc = relu(word @ Ww + bw)   [384,512] K=512
    gemm_f16k<true, true, 0><<<dim3(HD / 128, (BB * LL) / 64), 256, GF_SMEM>>>(
        word, Ww, bw, henc, nullptr, BB * LL, HD, WDIM);

    // 2) frame encoder: v = relu(frame @ Wf + bf)    [2048,512] K=1024
    gemm_f16k<true, true, 1><<<dim3(HD / 128, (BB * TT) / 64), 256, GF_SMEM>>>(
        frame, Wf, bf, v, flen, BB * TT, HD, FDIM);

    // 3) fused attention (fp16 mainloop, 2 CTAs/SM)
    int write_h2v = (out_size >= OUT_OFF + H2V_ELEMS) ? 1 : 0;
    attn_v9<<<dim3(1, BB * 256), 512, AT_SMEM>>>(
        Wa, word, flen, wlen, out + OUT_OFF, write_h2v);

    // 4) out = fww @ Wout    [2048,512] K=512; masked t tiles are exact zeros
    gemm_f16k<false, false, 2><<<dim3(OD / 128, (BB * TT) / 64), 256, GF_SMEM>>>(
        fww, Wout, nullptr, out, flen, BB * TT, OD, HD);
}

// round 17
// speedup vs baseline: 2.0782x; 2.0782x over previous
#include <cuda_runtime.h>
#include <cuda_fp16.h>
#include <cstdint>

#define BB 8
#define TT 256
#define LL 48
#define FDIM 1024
#define WDIM 512
#define HD 512
#define OD 512
#define OUT_OFF (BB*TT*OD)                 /* 1048576 floats */
#define H2V_ELEMS (BB*TT*LL*HD)            /* 50331648 floats */

// ---------------- scratch (no allocations allowed) ----------------
__device__ float g_henc[BB*LL*HD];         // relu(word @ Ww + bw)
__device__ float g_v[BB*TT*HD];            // relu(frame @ Wf + bf)
__device__ float g_fww[BB*TT*HD];          // sum_l h2v * word

// ---------------- helpers ----------------
__device__ __forceinline__ float tanh_fast(float x) {
    float y; asm("tanh.approx.f32 %0, %1;" : "=f"(y) : "f"(x)); return y;
}
__device__ __forceinline__ uint32_t pack_h2(float lo, float hi) {
    __half2 h = __floats2half2_rn(lo, hi);
    return *(uint32_t*)&h;
}
__device__ __forceinline__ void mma_f16(float* c, const uint32_t* a,
                                        uint32_t b0, uint32_t b1) {
    asm volatile("mma.sync.aligned.m16n8k16.row.col.f32.f16.f16.f32 "
                 "{%0,%1,%2,%3}, {%4,%5,%6,%7}, {%8,%9}, {%0,%1,%2,%3};"
                 : "+f"(c[0]), "+f"(c[1]), "+f"(c[2]), "+f"(c[3])
                 : "r"(a[0]), "r"(a[1]), "r"(a[2]), "r"(a[3]),
                   "r"(b0), "r"(b1));
}

// ======== fp16 tensor-core GEMM: 64x128 tile, triple-buffer, masked =======
// (byte-identical to R13 — known good)
#define GF_AS 1280     /* 64*20 u32 per buffer */
#define GF_BS 2176     /* 16*136 u32 per buffer */
#define GF_SMEM ((3*GF_AS + 3*GF_BS)*4)    /* 41472 bytes */

template<bool RELU, bool BIAS, int MASK>
__global__ __launch_bounds__(256) void gemm_f16k(
    const float* __restrict__ A, const float* __restrict__ W,
    const float* __restrict__ bias, float* __restrict__ C,
    const int* __restrict__ flen, int M, int N, int K)
{
    extern __shared__ uint32_t smu[];
    uint32_t* As = smu;                 // 3 buffers [64][20]
    uint32_t* Bs = smu + 3*GF_AS;       // 3 buffers [16][136]
    const int tid = threadIdx.x;
    const int m0 = blockIdx.y * 64, n0 = blockIdx.x * 128;

    if (MASK) {
        int bt = m0 >> 8, tloc = m0 & 255;
        if (tloc >= flen[bt]) {
            if (MASK == 2) {
                float4 z = make_float4(0.f, 0.f, 0.f, 0.f);
                for (int i = tid; i < 64 * 32; i += 256) {
                    int r = i >> 5, c4 = (i & 31) << 2;
                    *(float4*)(C + (size_t)(m0 + r) * N + n0 + c4) = z;
                }
            }
            return;
        }
    }

    const int lane = tid & 31, wid = tid >> 5;
    const int g = lane >> 2, tig = lane & 3;
    const int wm = wid & 1, wn = wid >> 1;
    const int warp_m0 = wm * 32, warp_n0 = wn * 32;

    const int ar0 = tid >> 3,         ak0 = (tid & 7) << 2;
    const int ar1 = (tid + 256) >> 3, ak1 = ((tid + 256) & 7) << 2;
    const int bk0 = tid >> 5;
    const int bnq = (tid & 31) << 2;

    float c[2][4][4];
    #pragma unroll
    for (int mi = 0; mi < 2; ++mi)
        #pragma unroll
        for (int nf = 0; nf < 4; ++nf)
            #pragma unroll
            for (int j = 0; j < 4; ++j) c[mi][nf][j] = 0.f;

    struct Stage { float4 ra0, ra1, b0a, b0b, b1a, b1b; };
    Stage s0, s1;

    auto ldg_chunk = [&](int k0, Stage& st) {
        st.ra0 = *(const float4*)(A + (size_t)(m0 + ar0) * K + k0 + ak0);
        st.ra1 = *(const float4*)(A + (size_t)(m0 + ar1) * K + k0 + ak1);
        st.b0a = *(const float4*)(W + (size_t)(k0 + 2*bk0)      * N + n0 + bnq);
        st.b0b = *(const float4*)(W + (size_t)(k0 + 2*bk0 + 1)  * N + n0 + bnq);
        st.b1a = *(const float4*)(W + (size_t)(k0 + 2*(bk0+8))     * N + n0 + bnq);
        st.b1b = *(const float4*)(W + (size_t)(k0 + 2*(bk0+8) + 1) * N + n0 + bnq);
    };
    auto sts_chunk = [&](const Stage& st, int bsel) {
        uint32_t* as = As + bsel * GF_AS;
        uint32_t* bs = Bs + bsel * GF_BS;
        *(uint2*)&as[ar0 * 20 + (ak0 >> 1)] =
            make_uint2(pack_h2(st.ra0.x, st.ra0.y), pack_h2(st.ra0.z, st.ra0.w));
        *(uint2*)&as[ar1 * 20 + (ak1 >> 1)] =
            make_uint2(pack_h2(st.ra1.x, st.ra1.y), pack_h2(st.ra1.z, st.ra1.w));
        uint4 p0, p1;
        p0.x = pack_h2(st.b0a.x, st.b0b.x); p0.y = pack_h2(st.b0a.y, st.b0b.y);
        p0.z = pack_h2(st.b0a.z, st.b0b.z); p0.w = pack_h2(st.b0a.w, st.b0b.w);
        p1.x = pack_h2(st.b1a.x, st.b1b.x); p1.y = pack_h2(st.b1a.y, st.b1b.y);
        p1.z = pack_h2(st.b1a.z, st.b1b.z); p1.w = pack_h2(st.b1a.w, st.b1b.w);
        *(uint4*)&bs[bk0 * 136 + bnq]       = p0;
        *(uint4*)&bs[(bk0 + 8) * 136 + bnq] = p1;
    };
    auto mma_chunk = [&](int bsel) {
        const uint32_t* as = As + bsel * GF_AS;
        const uint32_t* bs = Bs + bsel * GF_BS;
        #pragma unroll
        for (int ks = 0; ks < 2; ++ks) {
            const int base = ks * 8;
            uint32_t a[2][4];
            #pragma unroll
            for (int mi = 0; mi < 2; ++mi) {
                int r0 = warp_m0 + mi * 16;
                a[mi][0] = as[(r0 + g)     * 20 + base + tig];
                a[mi][1] = as[(r0 + 8 + g) * 20 + base + tig];
                a[mi][2] = as[(r0 + g)     * 20 + base + tig + 4];
                a[mi][3] = as[(r0 + 8 + g) * 20 + base + tig + 4];
            }
            #pragma unroll
            for (int nf = 0; nf < 4; ++nf) {
                int cc = warp_n0 + nf * 8 + g;
                uint32_t b0 = bs[(base + tig)     * 136 + cc];
                uint32_t b1 = bs[(base + tig + 4) * 136 + cc];
                mma_f16(c[0][nf], a[0], b0, b1);
                mma_f16(c[1][nf], a[1], b0, b1);
            }
        }
    };

    const int nch = K >> 5;
    ldg_chunk(0, s0);
    sts_chunk(s0, 0);
    if (nch > 1) ldg_chunk(32, s1);
    __syncthreads();

    int bcur = 0, bnxt = 1, bnxt2 = 2;
    for (int gch = 0; gch < nch; gch += 2) {
        if (gch + 2 < nch) ldg_chunk((gch + 2) << 5, s0);
        mma_chunk(bcur);
        if (gch + 1 < nch) sts_chunk(s1, bnxt);
        __syncthreads();
        if (gch + 3 < nch) ldg_chunk((gch + 3) << 5, s1);
        if (gch + 1 < nch) mma_chunk(bnxt);
        if (gch + 2 < nch) sts_chunk(s0, bnxt2);
        __syncthreads();
        int t = bcur; bcur = bnxt2; bnxt2 = bnxt; bnxt = t;
    }

    #pragma unroll
    for (int mi = 0; mi < 2; ++mi) {
        #pragma unroll
        for (int nf = 0; nf < 4; ++nf) {
            int r0 = m0 + warp_m0 + mi * 16 + g;
            int cc = n0 + warp_n0 + nf * 8 + tig * 2;
            float o0 = c[mi][nf][0], o1 = c[mi][nf][1];
            float o2 = c[mi][nf][2], o3 = c[mi][nf][3];
            if (BIAS) {
                float bb0 = bias[cc], bb1 = bias[cc + 1];
                o0 += bb0; o1 += bb1; o2 += bb0; o3 += bb1;
            }
            if (RELU) {
                o0 = fmaxf(o0, 0.f); o1 = fmaxf(o1, 0.f);
                o2 = fmaxf(o2, 0.f); o3 = fmaxf(o3, 0.f);
            }
            *(float2*)(C + (size_t)r0 * N + cc)       = make_float2(o0, o1);
            *(float2*)(C + (size_t)(r0 + 8) * N + cc) = make_float2(o2, o3);
        }
    }
}

// ========== fused attention v11: k32 B chunks, double-buffered =============
// R13 structure with B chunk widened k16 -> k32 (two k16 sub-steps per
// buffer): mma block per buffer ~2x longer, hiding LDG latency with the
// existing 1-deep register prefetch; syncthreads count halves (32 -> 16).
#define AT_AM_U32  0                     /* 64*260 = 16640 u32 */
#define AT_B_U32   16640                 /* 2*16*520 = 16640 u32 */
#define AT_VT_F32  33280                 /* 2048 f32 */
#define AT_SMEM    ((33280 + 2048) * 4)  /* 141312 bytes */
#define R_STRIDE   264

__global__ __launch_bounds__(512, 1) void attn_v11(
    const float* __restrict__ Wa, const float* __restrict__ word,
    const int* __restrict__ flen, const int* __restrict__ wlen,
    float* __restrict__ h2v_all, int write_h2v)
{
    extern __shared__ float sm[];
    const int tid = threadIdx.x;
    const int b  = blockIdx.y >> 8;
    const int yl = blockIdx.y & 255;
    const int fl = flen[b];

    int Lv = wlen[b]; if (Lv > LL) Lv = LL;
    const int lpsh = (Lv <= 16) ? 4 : (Lv <= 32) ? 5 : 6;
    const int lpmask = (1 << lpsh) - 1;
    const int TPB = 64 >> lpsh;                // 4 / 2 / 1
    const int t0 = yl * TPB;
    if (t0 >= TT) return;

    float* h2v = write_h2v ? h2v_all : nullptr;

    if (t0 >= fl) {       // fully masked t's: exact zeros
        float4 z = make_float4(0.f, 0.f, 0.f, 0.f);
        if (h2v) {
            for (int i = tid; i < TPB * LL * 128; i += 512) {
                int t = i / (LL * 128);
                int rem = i - t * (LL * 128);
                int l = rem >> 7, c4 = (rem & 127) << 2;
                *(float4*)&h2v[((size_t)(b * TT + t0 + t) * LL + l) * HD + c4] = z;
            }
        }
        for (int i = tid; i < TPB * 128; i += 512) {
            int t = i >> 7, c4 = (i & 127) << 2;
            *(float4*)&g_fww[(size_t)(b * TT + t0 + t) * HD + c4] = z;
        }
        return;
    }

    uint32_t* Am = (uint32_t*)sm + AT_AM_U32;     // [64][260]
    uint32_t* Bb = (uint32_t*)sm + AT_B_U32;      // 2 x [16][520]
    float*    vt = sm + AT_VT_F32;
    float*    R  = sm;                            // overlay, [64][264]

    // stage v rows
    for (int i = tid; i < TPB * 128; i += 512) {
        int tl = i >> 7, c4 = (i & 127) << 2;
        *(float4*)&vt[tl * 512 + c4] =
            *(const float4*)&g_v[(size_t)(b * TT + t0 + tl) * HD + c4];
    }
    __syncthreads();

    // build A once: tanh(v + henc) -> half2 k-pairs; zero padded l rows
    for (int i = tid; i < 64 * 128; i += 512) {
        int r = i >> 7, c4 = (i & 127) << 2;
        int tl = r >> lpsh, l = r & lpmask;
        uint2 pk = make_uint2(0u, 0u);
        if (l < Lv) {
            float4 hv = *(const float4*)&g_henc[(size_t)(b * LL + l) * HD + c4];
            const float* vp = &vt[tl * 512 + c4];
            float v0 = tanh_fast(vp[0] + hv.x);
            float v1 = tanh_fast(vp[1] + hv.y);
            float v2 = tanh_fast(vp[2] + hv.z);
            float v3 = tanh_fast(vp[3] + hv.w);
            pk.x = pack_h2(v0, v1);
            pk.y = pack_h2(v2, v3);
        }
        *(uint2*)&Am[r * 260 + (c4 >> 1)] = pk;
    }
    __syncthreads();

    const int lane = tid & 31, wid = tid >> 5;           // 16 warps
    const int g = lane >> 2, tig = lane & 3;
    const int wm = wid & 1, wn = wid >> 1;               // 2m x 8n
    const int warp_m0 = wm * 32, warp_n0 = wn * 64;
    const bool skip_hi = (lpsh == 6) && (wm == 1);

    float c[2][8][4];
    #pragma unroll
    for (int mi = 0; mi < 2; ++mi)
        #pragma unroll
        for (int nf = 0; nf < 8; ++nf)
            #pragma unroll
            for (int j = 0; j < 4; ++j) c[mi][nf][j] = 0.f;

    // B chunk = k32 = 16 k2-rows x 512 cols = 2048 uint4 slots -> 4/thread
    const int bk2 = tid >> 7;                  // base k2 row 0..3 (+ii*4)
    const int bnq = (tid & 127) << 2;          // col 0..508
    float4 rbA[4], rbB[4];

    auto ldgB = [&](int gch) {
        const int k0 = gch << 5;               // 32 k per chunk
        #pragma unroll
        for (int ii = 0; ii < 4; ++ii) {
            int k2r = bk2 + ii * 4;            // 0..15
            rbA[ii] = *(const float4*)&Wa[(size_t)(k0 + 2*k2r)     * HD + bnq];
            rbB[ii] = *(const float4*)&Wa[(size_t)(k0 + 2*k2r + 1) * HD + bnq];
        }
    };
    auto stsB = [&](int bsel) {
        uint32_t* bs = Bb + bsel * (16 * 520);
        #pragma unroll
        for (int ii = 0; ii < 4; ++ii) {
            int k2r = bk2 + ii * 4;
            uint4 p;
            p.x = pack_h2(rbA[ii].x, rbB[ii].x);
            p.y = pack_h2(rbA[ii].y, rbB[ii].y);
            p.z = pack_h2(rbA[ii].z, rbB[ii].z);
            p.w = pack_h2(rbA[ii].w, rbB[ii].w);
            *(uint4*)&bs[k2r * 520 + bnq] = p;
        }
    };
    auto mmaB = [&](int bsel, int gch) {
        const uint32_t* bs = Bb + bsel * (16 * 520);
        #pragma unroll
        for (int ks = 0; ks < 2; ++ks) {       // two k16 sub-steps
            const int kof2 = (gch << 4) + ks * 8;   // k2 offset into Am
            const int kl = ks * 8;                  // local k2 offset into bs
            uint32_t a[2][4];
            #pragma unroll
            for (int mi = 0; mi < 2; ++mi) {
                int r0 = warp_m0 + mi * 16;
                a[mi][0] = Am[(r0 + g)     * 260 + kof2 + tig];
                a[mi][1] = Am[(r0 + 8 + g) * 260 + kof2 + tig];
                a[mi][2] = Am[(r0 + g)     * 260 + kof2 + tig + 4];
                a[mi][3] = Am[(r0 + 8 + g) * 260 + kof2 + tig + 4];
            }
            #pragma unroll
            for (int nf = 0; nf < 8; ++nf) {
                int cc = warp_n0 + nf * 8 + g;
                uint32_t b0 = bs[(kl + tig)     * 520 + cc];
                uint32_t b1 = bs[(kl + tig + 4) * 520 + cc];
                mma_f16(c[0][nf], a[0], b0, b1);
                if (!skip_hi) mma_f16(c[1][nf], a[1], b0, b1);
            }
        }
    };

    // 16 chunks of k32, double-buffered, 1-deep register prefetch
    ldgB(0);
    stsB(0);
    __syncthreads();
    for (int gch = 0; gch < 16; ++gch) {
        if (gch < 15) ldgB(gch + 1);
        mmaB(gch & 1, gch);
        if (gch < 15) stsB((gch + 1) & 1);
        __syncthreads();
    }

    // epilogue in two 256-col halves (R overlays dead A/B smem)
    const int myhalf = wn >> 2;
    for (int h = 0; h < 2; ++h) {
        if (myhalf == h) {
            #pragma unroll
            for (int mi = 0; mi < 2; ++mi) {
                if (mi == 1 && skip_hi) break;
                #pragma unroll
                for (int nf = 0; nf < 8; ++nf) {
                    int rr0 = warp_m0 + mi * 16 + g;
                    int cl  = (warp_n0 & 255) + nf * 8 + tig * 2;
                    *(float2*)&R[rr0 * R_STRIDE + cl] =
                        make_float2(fmaxf(c[mi][nf][0], 0.f), fmaxf(c[mi][nf][1], 0.f));
                    *(float2*)&R[(rr0 + 8) * R_STRIDE + cl] =
                        make_float2(fmaxf(c[mi][nf][2], 0.f), fmaxf(c[mi][nf][3], 0.f));
                }
            }
        }
        __syncthreads();

        const int col = tid & 255;
        const int tgpar = tid >> 8;
        for (int tg = tgpar; tg < TPB; tg += 2) {
            const int t = t0 + tg;
            const int rb2 = tg << lpsh;
            const int hg = h * 256 + col;
            float* hp = h2v ? (h2v + ((size_t)(b * TT + t) * LL) * HD + hg) : nullptr;
            if (t < fl) {
                float mx = 0.f;
                for (int l = 0; l < Lv; ++l)
                    mx = fmaxf(mx, R[(rb2 + l) * R_STRIDE + col]);
                float sum = 0.f;
                for (int l = 0; l < Lv; ++l) {
                    float e = __expf(R[(rb2 + l) * R_STRIDE + col] - mx);
                    sum += e;
                    R[(rb2 + l) * R_STRIDE + col] = e;
                }
                float inv = 1.0f / sum;
                const float* wp = word + ((size_t)b * LL) * WDIM + hg;
                float fww = 0.f;
                for (int l = 0; l < Lv; ++l) {
                    float w = R[(rb2 + l) * R_STRIDE + col] * inv;
                    if (hp) hp[(size_t)l * HD] = w;
                    fww += w * wp[(size_t)l * WDIM];
                }
                if (hp)
                    for (int l = Lv; l < LL; ++l) hp[(size_t)l * HD] = 0.f;
                g_fww[(size_t)(b * TT + t) * HD + hg] = fww;
            } else {
                if (hp)
                    for (int l = 0; l < LL; ++l) hp[(size_t)l * HD] = 0.f;
                g_fww[(size_t)(b * TT + t) * HD + hg] = 0.f;
            }
        }
        __syncthreads();
    }
}

// ---------------- launcher ----------------
extern "C" void kernel_launch(void* const* d_in, const int* in_sizes, int n_in,
                              void* d_out, int out_size) {
    const float* frame = (const float*)d_in[0];
    const float* word  = (const float*)d_in[1];
    const int*   flen  = (const int*)  d_in[2];
    const int*   wlen  = (const int*)  d_in[3];
    const float* Wf    = (const float*)d_in[4];
    const float* bf    = (const float*)d_in[5];
    const float* Ww    = (const float*)d_in[6];
    const float* bw    = (const float*)d_in[7];
    const float* Wa    = (const float*)d_in[8];
    const float* Wout  = (const float*)d_in[9];
    float* out = (float*)d_out;

    float *henc, *v, *fww;
    cudaGetSymbolAddress((void**)&henc, g_henc);
    cudaGetSymbolAddress((void**)&v,    g_v);
    cudaGetSymbolAddress((void**)&fww,  g_fww);

    cudaFuncSetAttribute(gemm_f16k<true, true, 0>,
                         cudaFuncAttributeMaxDynamicSharedMemorySize, GF_SMEM);
    cudaFuncSetAttribute(gemm_f16k<true, true, 1>,
                         cudaFuncAttributeMaxDynamicSharedMemorySize, GF_SMEM);
    cudaFuncSetAttribute(gemm_f16k<false, false, 2>,
                         cudaFuncAttributeMaxDynamicSharedMemorySize, GF_SMEM);
    cudaFuncSetAttribute(attn_v11,
                         cudaFuncAttributeMaxDynamicSharedMemorySize, AT_SMEM);

    // 1) word encoder: henc = relu(word @ Ww + bw)   [384,512] K=512
    gemm_f16k<true, true, 0><<<dim3(HD / 128, (BB * LL) / 64), 256, GF_SMEM>>>(
        word, Ww, bw, henc, nullptr, BB * LL, HD, WDIM);

    // 2) frame encoder: v = relu(frame @ Wf + bf)    [2048,512] K=1024
    gemm_f16k<true, true, 1><<<dim3(HD / 128, (BB * TT) / 64), 256, GF_SMEM>>>(
        frame, Wf, bf, v, flen, BB * TT, HD, FDIM);

    // 3) fused attention (fp16 mainloop, k32 double-buffered B)
    int write_h2v = (out_size >= OUT_OFF + H2V_ELEMS) ? 1 : 0;
    attn_v11<<<dim3(1, BB * 256), 512, AT_SMEM>>>(
        Wa, word, flen, wlen, out + OUT_OFF, write_h2v);

    // 4) out = fww @ Wout    [2048,512] K=512; masked t tiles are exact zeros
    gemm_f16k<false, false, 2><<<dim3(OD / 128, (BB * TT) / 64), 256, GF_SMEM>>>(
        fww, Wout, nullptr, out, flen, BB * TT, OD, HD);
}